// round 11
// baseline (speedup 1.0000x reference)
#include <cuda_runtime.h>
#include <math.h>

#define LSEQ  4096
#define HID   512
#define GATES 2048
#define TTAG  24
#define NBLK  64      // CTAs per direction in recurrence
#define EDIM  300

typedef unsigned long long ull;

// ---------------- scratch (static device arrays: no allocation) ----------------
__device__ __align__(16) float g_x[(size_t)LSEQ * EDIM];
__device__ __align__(16) float g_preA[(size_t)LSEQ * GATES];
__device__ __align__(16) float g_preB[(size_t)LSEQ * GATES];
__device__ __align__(16) float g_hs0[(size_t)LSEQ * 1024];
__device__ __align__(16) float g_hs1[(size_t)LSEQ * 1024];
__device__ __align__(16) float g_emis[(size_t)LSEQ * TTAG];
// per-step h exchange: packed {tag,h} 8B words: [layer][dir][t][512]
__device__ __align__(16) ull g_hbuf[(size_t)2 * 2 * LSEQ * HID];

// ---------------- tag reset (runs first every replay) ----------------
__global__ void fill_tags()
{
    uint4 z = make_uint4(0u, 0u, 0u, 0u);
    size_t n16 = ((size_t)2 * 2 * LSEQ * HID * 8) >> 4;
    uint4* p = (uint4*)g_hbuf;
    for (size_t i = (size_t)blockIdx.x * blockDim.x + threadIdx.x; i < n16;
         i += (size_t)gridDim.x * blockDim.x)
        p[i] = z;
}

// ---------------- embedding gather ----------------
__global__ void gather_kernel(const float* __restrict__ emb, const int* __restrict__ sent)
{
    int t = blockIdx.x;
    int s = sent[t];
    const float* src = emb + (size_t)s * EDIM;
    float* dst = g_x + (size_t)t * EDIM;
    for (int e = threadIdx.x; e < EDIM; e += blockDim.x) dst[e] = src[e];
}

// ---------------- fp32 SGEMM:  C[M,N] = A[M,K] * B[N,K]^T + bias[N] ----------------
__global__ __launch_bounds__(256) void sgemm_nt(
    int M, int N, int K,
    const float* __restrict__ A, int lda,
    const float* __restrict__ B, int ldb,
    const float* __restrict__ bias,
    float* __restrict__ C, int ldc)
{
    __shared__ float As[8][128];
    __shared__ float Bs[8][128];
    const int tid = threadIdx.x;
    const int tx = tid & 15;
    const int ty = tid >> 4;
    const int m0 = blockIdx.y * 128;
    const int n0 = blockIdx.x * 128;
    const int lr = tid >> 1;
    const int lc = (tid & 1) * 4;

    float acc[8][8];
#pragma unroll
    for (int i2 = 0; i2 < 8; i2++)
#pragma unroll
        for (int j2 = 0; j2 < 8; j2++) acc[i2][j2] = 0.f;

    const int nkt = (K + 7) >> 3;
    for (int kt = 0; kt < nkt; kt++){
        const int k0 = kt << 3;
        const int kc = k0 + lc;
        float4 av = make_float4(0.f,0.f,0.f,0.f);
        {
            int r = m0 + lr;
            if (r < M){
                if (kc + 3 < K) av = *(const float4*)(A + (size_t)r * lda + kc);
                else {
                    if (kc + 0 < K) av.x = A[(size_t)r * lda + kc + 0];
                    if (kc + 1 < K) av.y = A[(size_t)r * lda + kc + 1];
                    if (kc + 2 < K) av.z = A[(size_t)r * lda + kc + 2];
                    if (kc + 3 < K) av.w = A[(size_t)r * lda + kc + 3];
                }
            }
        }
        float4 bv = make_float4(0.f,0.f,0.f,0.f);
        {
            int r = n0 + lr;
            if (r < N){
                if (kc + 3 < K) bv = *(const float4*)(B + (size_t)r * ldb + kc);
                else {
                    if (kc + 0 < K) bv.x = B[(size_t)r * ldb + kc + 0];
                    if (kc + 1 < K) bv.y = B[(size_t)r * ldb + kc + 1];
                    if (kc + 2 < K) bv.z = B[(size_t)r * ldb + kc + 2];
                    if (kc + 3 < K) bv.w = B[(size_t)r * ldb + kc + 3];
                }
            }
        }
        As[lc + 0][lr] = av.x; As[lc + 1][lr] = av.y; As[lc + 2][lr] = av.z; As[lc + 3][lr] = av.w;
        Bs[lc + 0][lr] = bv.x; Bs[lc + 1][lr] = bv.y; Bs[lc + 2][lr] = bv.z; Bs[lc + 3][lr] = bv.w;
        __syncthreads();
#pragma unroll
        for (int k = 0; k < 8; k++){
            float a[8], b[8];
            *(float4*)&a[0] = *(const float4*)&As[k][ty * 8];
            *(float4*)&a[4] = *(const float4*)&As[k][ty * 8 + 4];
            *(float4*)&b[0] = *(const float4*)&Bs[k][tx * 8];
            *(float4*)&b[4] = *(const float4*)&Bs[k][tx * 8 + 4];
#pragma unroll
            for (int i2 = 0; i2 < 8; i2++)
#pragma unroll
                for (int j2 = 0; j2 < 8; j2++)
                    acc[i2][j2] = fmaf(a[i2], b[j2], acc[i2][j2]);
        }
        __syncthreads();
    }
#pragma unroll
    for (int i2 = 0; i2 < 8; i2++){
        int m = m0 + ty * 8 + i2;
        if (m < M){
#pragma unroll
            for (int j2 = 0; j2 < 8; j2++){
                int n = n0 + tx * 8 + j2;
                if (n < N) C[(size_t)m * ldc + n] = acc[i2][j2] + bias[n];
            }
        }
    }
}

// ---------------- fast math helpers ----------------
__device__ __forceinline__ ull fma2(ull a, ull b, ull c)
{
    ull d;
    asm("fma.rn.f32x2 %0, %1, %2, %3;" : "=l"(d) : "l"(a), "l"(b), "l"(c));
    return d;
}
__device__ __forceinline__ float lo32f(ull v){ return __uint_as_float((unsigned)v); }
__device__ __forceinline__ float hi32f(ull v){ return __uint_as_float((unsigned)(v >> 32)); }
__device__ __forceinline__ float tanh_fast(float x)
{
    float y;
    asm("tanh.approx.f32 %0, %1;" : "=f"(y) : "f"(x));
    return y;
}
__device__ __forceinline__ float sigm_fast(float x)
{
    return fmaf(0.5f, tanh_fast(0.5f * x), 0.5f);
}

// ---------------- bidirectional LSTM recurrence (one layer, both directions) ----------------
// R8 structure (best known). Deltas: pipelined 2-stream poll (halved detect period);
// tanh.approx activation tail (shortened serial chain).
__global__ __launch_bounds__(256, 1) void lstm_rec(
    const float* __restrict__ preF, const float* __restrict__ preB,
    const float* __restrict__ whhF, const float* __restrict__ whhB,
    float* __restrict__ hsOut,      // [L,1024], fwd -> 0..511, bwd -> 512..1023
    ull* __restrict__ hb)           // [2 dirs][LSEQ][512] packed {tag,h}
{
    const int dir = blockIdx.x >> 6;
    const int blk = blockIdx.x & 63;
    const float* pre = dir ? preB : preF;
    const float* whh = dir ? whhB : whhF;
    ull* hbd = hb + (size_t)dir * LSEQ * HID;

    const int tid  = threadIdx.x;
    const int row  = tid >> 3;          // 0..31 local gate row
    const int cs   = tid & 7;           // 0..7 column slice
    const int gate = row >> 3;          // 0..3 (i,f,g,o)
    const int ii   = row & 7;           // 0..7 h index within CTA
    const int grow = gate * HID + blk * 8 + ii;

    // register-resident packed weight slice: whh[grow][cs*64 .. cs*64+64) as 32 f32x2
    ull wpk[32];
    {
        const float2* wr = (const float2*)(whh + (size_t)grow * HID + cs * 64);
#pragma unroll
        for (int k = 0; k < 32; k++){
            float2 v = wr[k];
            wpk[k] = ((ull)__float_as_uint(v.y) << 32) | (ull)__float_as_uint(v.x);
        }
    }

    __shared__ __align__(16) float sh_h[8 * 68];   // 64-blocks padded by 4 floats
    __shared__ float sg[32];
    for (int k = tid; k < 8 * 68; k += 256) sh_h[k] = 0.f;
    float c = 0.f;                                  // cell state (threads tid<8)
    __syncthreads();

    float preCur = 0.f;
    if (cs == 0){
        int tt0 = dir ? (LSEQ - 1) : 0;
        preCur = pre[(size_t)tt0 * GATES + grow];
    }

    for (int t = 0; t < LSEQ; t++){
        const int tt = dir ? (LSEQ - 1 - t) : t;

        // ---- acquire h(t-1): two interleaved in-flight poll streams (halved detect period) ----
        if (t > 0){
            const ull* p = hbd + (size_t)(t - 1) * HID + 2 * tid;  // 16B aligned
            const unsigned expTag = (unsigned)t;
            ull a0, a1, b0, b1, r0, r1;
            asm volatile("ld.global.cg.v2.b64 {%0,%1}, [%2];" : "=l"(a0), "=l"(a1) : "l"(p) : "memory");
            asm volatile("ld.global.cg.v2.b64 {%0,%1}, [%2];" : "=l"(b0), "=l"(b1) : "l"(p) : "memory");
            for (;;){
                if ((unsigned)(a0 >> 32) == expTag && (unsigned)(a1 >> 32) == expTag){ r0 = a0; r1 = a1; break; }
                asm volatile("ld.global.cg.v2.b64 {%0,%1}, [%2];" : "=l"(a0), "=l"(a1) : "l"(p) : "memory");
                if ((unsigned)(b0 >> 32) == expTag && (unsigned)(b1 >> 32) == expTag){ r0 = b0; r1 = b1; break; }
                asm volatile("ld.global.cg.v2.b64 {%0,%1}, [%2];" : "=l"(b0), "=l"(b1) : "l"(p) : "memory");
            }
            *(float2*)(sh_h + 2 * tid + 4 * (tid >> 5)) =
                make_float2(__uint_as_float((unsigned)r0), __uint_as_float((unsigned)r1));
        }
        __syncthreads();

        // prefetch next step's pre-activation (overlaps with the dot product)
        float preNext = 0.f;
        if (cs == 0 && t + 1 < LSEQ){
            int ttn = dir ? (LSEQ - 2 - t) : (t + 1);
            preNext = pre[(size_t)ttn * GATES + grow];
        }

        // 64-wide slice of the 512-dot: 32 packed f32x2 FMAs over 4 accumulators
        ull a0 = 0ull, a1 = 0ull, a2 = 0ull, a3 = 0ull;
        {
            const ulonglong2* hp = (const ulonglong2*)(sh_h + cs * 68);
#pragma unroll
            for (int k = 0; k < 8; k += 4){
                ulonglong2 u0 = hp[k + 0], u1 = hp[k + 1], u2 = hp[k + 2], u3 = hp[k + 3];
                a0 = fma2(wpk[4*k + 0], u0.x, a0); a0 = fma2(wpk[4*k + 1], u0.y, a0);
                a1 = fma2(wpk[4*k + 2], u1.x, a1); a1 = fma2(wpk[4*k + 3], u1.y, a1);
                a2 = fma2(wpk[4*k + 4], u2.x, a2); a2 = fma2(wpk[4*k + 5], u2.y, a2);
                a3 = fma2(wpk[4*k + 6], u3.x, a3); a3 = fma2(wpk[4*k + 7], u3.y, a3);
            }
        }
        float sum = ((lo32f(a0) + hi32f(a0)) + (lo32f(a1) + hi32f(a1)))
                  + ((lo32f(a2) + hi32f(a2)) + (lo32f(a3) + hi32f(a3)));
        sum += __shfl_down_sync(0xffffffffu, sum, 4);
        sum += __shfl_down_sync(0xffffffffu, sum, 2);
        sum += __shfl_down_sync(0xffffffffu, sum, 1);
        if (cs == 0) sg[row] = sum + preCur;
        __syncthreads();

        if (tid < 8){
            float zi = sg[tid], zf = sg[8 + tid], zg = sg[16 + tid], zo = sg[24 + tid];
            float ig = sigm_fast(zi);
            float fg = sigm_fast(zf);
            float og = sigm_fast(zo);
            float tg = tanh_fast(zg);
            c = fg * c + ig * tg;
            float h = og * tanh_fast(c);
            int hidx = blk * 8 + tid;
            ull v = ((ull)(unsigned)(t + 1) << 32) | (ull)__float_as_uint(h);
            asm volatile("st.global.cg.b64 [%0], %1;"
                         :: "l"(hbd + (size_t)t * HID + hidx), "l"(v) : "memory");
            hsOut[(size_t)tt * 1024 + dir * HID + hidx] = h;
        }
        preCur = preNext;
    }
}

// ---------------- CRF negative log-likelihood ----------------
// block (32,24): warp j computes alpha_new[j] each step; shfl.bfly reductions
// (redux.sync.f32 does NOT exist on sm_103). Double-buffered alpha: one sync/step.
__global__ void crf_kernel(const float* __restrict__ emis, const int* __restrict__ tags,
                           const float* __restrict__ startT, const float* __restrict__ endT,
                           const float* __restrict__ trans, float* __restrict__ out)
{
    const int i = threadIdx.x;   // 0..31 (prev tag lane)
    const int j = threadIdx.y;   // 0..23 (current tag)
    const int tid = j * 32 + i;
    __shared__ float alpha[2][TTAG];
    __shared__ float red[TTAG];

    // numerator (gold path score), parallel over t
    float acc = 0.f;
    for (int t = tid; t < LSEQ; t += 768){
        acc += emis[t * TTAG + tags[t]];
        if (t > 0) acc += trans[tags[t - 1] * TTAG + tags[t]];
    }
#pragma unroll
    for (int d = 16; d; d >>= 1) acc += __shfl_xor_sync(0xffffffffu, acc, d);
    if (i == 0) red[j] = acc;

    const float trj = (i < TTAG) ? trans[i * TTAG + j] : 0.f;
    if (i == 0) alpha[0][j] = startT[j] + emis[j];
    __syncthreads();

    float num = 0.f;
    if (tid == 0){
        for (int q = 0; q < TTAG; q++) num += red[q];
        num += startT[tags[0]] + endT[tags[LSEQ - 1]];
    }

    for (int t = 1; t < LSEQ; t++){
        const int cur = (t - 1) & 1, nxt = t & 1;
        float v = (i < TTAG) ? (alpha[cur][i] + trj) : -3.0e38f;
        float m = v;
#pragma unroll
        for (int d = 16; d; d >>= 1) m = fmaxf(m, __shfl_xor_sync(0xffffffffu, m, d));
        float e = (i < TTAG) ? __expf(v - m) : 0.f;
#pragma unroll
        for (int d = 16; d; d >>= 1) e += __shfl_xor_sync(0xffffffffu, e, d);
        if (i == 0) alpha[nxt][j] = m + __logf(e) + emis[t * TTAG + j];
        __syncthreads();   // alpha[nxt] visible; alpha[cur] free for t+1's writes
    }

    if (tid == 0){
        const float* af = alpha[(LSEQ - 1) & 1];
        float m = -3.0e38f;
        for (int q = 0; q < TTAG; q++) m = fmaxf(m, af[q] + endT[q]);
        float s = 0.f;
        for (int q = 0; q < TTAG; q++) s += __expf(af[q] + endT[q] - m);
        out[0] = (m + __logf(s)) - num;
    }
}

// ---------------- launch ----------------
extern "C" void kernel_launch(void* const* d_in, const int* in_sizes, int n_in,
                              void* d_out, int out_size)
{
    (void)in_sizes; (void)n_in; (void)out_size;
    const float* emb    = (const float*)d_in[0];
    const float* wih0f  = (const float*)d_in[1];
    const float* whh0f  = (const float*)d_in[2];
    const float* b0f    = (const float*)d_in[3];
    const float* wih0b  = (const float*)d_in[4];
    const float* whh0b  = (const float*)d_in[5];
    const float* b0b    = (const float*)d_in[6];
    const float* wih1f  = (const float*)d_in[7];
    const float* whh1f  = (const float*)d_in[8];
    const float* b1f    = (const float*)d_in[9];
    const float* wih1b  = (const float*)d_in[10];
    const float* whh1b  = (const float*)d_in[11];
    const float* b1b    = (const float*)d_in[12];
    const float* wout   = (const float*)d_in[13];
    const float* bout   = (const float*)d_in[14];
    const float* startT = (const float*)d_in[15];
    const float* endT   = (const float*)d_in[16];
    const float* trans  = (const float*)d_in[17];
    const int*   sent   = (const int*)d_in[18];
    const int*   tags   = (const int*)d_in[19];

    float *x, *preA, *preB, *hs0, *hs1, *emis;
    ull* hbuf;
    cudaGetSymbolAddress((void**)&x,    g_x);
    cudaGetSymbolAddress((void**)&preA, g_preA);
    cudaGetSymbolAddress((void**)&preB, g_preB);
    cudaGetSymbolAddress((void**)&hs0,  g_hs0);
    cudaGetSymbolAddress((void**)&hs1,  g_hs1);
    cudaGetSymbolAddress((void**)&emis, g_emis);
    cudaGetSymbolAddress((void**)&hbuf, g_hbuf);

    // reset handshake tags + embedding gather
    fill_tags<<<4096, 256>>>();
    gather_kernel<<<LSEQ, 128>>>(emb, sent);

    // layer 0: input projections, then both-direction recurrence
    sgemm_nt<<<dim3(16, 32), 256>>>(LSEQ, GATES, EDIM, x, EDIM, wih0f, EDIM, b0f, preA, GATES);
    sgemm_nt<<<dim3(16, 32), 256>>>(LSEQ, GATES, EDIM, x, EDIM, wih0b, EDIM, b0b, preB, GATES);
    lstm_rec<<<2 * NBLK, 256>>>(preA, preB, whh0f, whh0b, hs0, hbuf);

    // layer 1
    sgemm_nt<<<dim3(16, 32), 256>>>(LSEQ, GATES, 1024, hs0, 1024, wih1f, 1024, b1f, preA, GATES);
    sgemm_nt<<<dim3(16, 32), 256>>>(LSEQ, GATES, 1024, hs0, 1024, wih1b, 1024, b1b, preB, GATES);
    lstm_rec<<<2 * NBLK, 256>>>(preA, preB, whh1f, whh1b, hs1, hbuf + (size_t)2 * LSEQ * HID);

    // emissions + CRF
    sgemm_nt<<<dim3(1, 32), 256>>>(LSEQ, TTAG, 1024, hs1, 1024, wout, 1024, bout, emis, TTAG);
    crf_kernel<<<1, dim3(32, 24)>>>(emis, tags, startT, endT, trans, (float*)d_out);
}

// round 12
// speedup vs baseline: 1.2865x; 1.2865x over previous
#include <cuda_runtime.h>
#include <math.h>

#define LSEQ  4096
#define HID   512
#define GATES 2048
#define TTAG  24
#define NBLK  64      // CTAs per direction in recurrence
#define EDIM  300

typedef unsigned long long ull;

// ---------------- scratch (static device arrays: no allocation) ----------------
__device__ __align__(16) float g_x[(size_t)LSEQ * EDIM];
__device__ __align__(16) float g_preA[(size_t)LSEQ * GATES];
__device__ __align__(16) float g_preB[(size_t)LSEQ * GATES];
__device__ __align__(16) float g_hs0[(size_t)LSEQ * 1024];
__device__ __align__(16) float g_hs1[(size_t)LSEQ * 1024];
__device__ __align__(16) float g_emis[(size_t)LSEQ * TTAG];
// per-step h exchange: packed {tag,h} 8B words: [layer][dir][t][512]
__device__ __align__(16) ull g_hbuf[(size_t)2 * 2 * LSEQ * HID];

// ---------------- packed f32x2 helpers ----------------
__device__ __forceinline__ ull fma2(ull a, ull b, ull c)
{
    ull d;
    asm("fma.rn.f32x2 %0, %1, %2, %3;" : "=l"(d) : "l"(a), "l"(b), "l"(c));
    return d;
}
__device__ __forceinline__ ull dup2(float x)
{
    ull r;
    asm("mov.b64 %0, {%1, %1};" : "=l"(r) : "f"(x));
    return r;
}
__device__ __forceinline__ float lo32f(ull v){ return __uint_as_float((unsigned)v); }
__device__ __forceinline__ float hi32f(ull v){ return __uint_as_float((unsigned)(v >> 32)); }

// ---------------- tag reset (runs first every replay) ----------------
__global__ void fill_tags()
{
    uint4 z = make_uint4(0u, 0u, 0u, 0u);
    size_t n16 = ((size_t)2 * 2 * LSEQ * HID * 8) >> 4;
    uint4* p = (uint4*)g_hbuf;
    for (size_t i = (size_t)blockIdx.x * blockDim.x + threadIdx.x; i < n16;
         i += (size_t)gridDim.x * blockDim.x)
        p[i] = z;
}

// ---------------- embedding gather ----------------
__global__ void gather_kernel(const float* __restrict__ emb, const int* __restrict__ sent)
{
    int t = blockIdx.x;
    int s = sent[t];
    const float* src = emb + (size_t)s * EDIM;
    float* dst = g_x + (size_t)t * EDIM;
    for (int e = threadIdx.x; e < EDIM; e += blockDim.x) dst[e] = src[e];
}

// ---------------- fp32 SGEMM (packed f32x2 inner product) ----------------
// C[M,N] = A[M,K] * B[N,K]^T + bias[N]
__global__ __launch_bounds__(256) void sgemm_nt(
    int M, int N, int K,
    const float* __restrict__ A, int lda,
    const float* __restrict__ B, int ldb,
    const float* __restrict__ bias,
    float* __restrict__ C, int ldc)
{
    __shared__ float As[8][128];
    __shared__ float Bs[8][128];
    const int tid = threadIdx.x;
    const int tx = tid & 15;
    const int ty = tid >> 4;
    const int m0 = blockIdx.y * 128;
    const int n0 = blockIdx.x * 128;
    const int lr = tid >> 1;
    const int lc = (tid & 1) * 4;

    // accumulators: 8 rows x 4 column-pairs, packed f32x2
    ull acc2[8][4];
#pragma unroll
    for (int i2 = 0; i2 < 8; i2++)
#pragma unroll
        for (int jp = 0; jp < 4; jp++) acc2[i2][jp] = 0ull;

    const int nkt = (K + 7) >> 3;
    for (int kt = 0; kt < nkt; kt++){
        const int k0 = kt << 3;
        const int kc = k0 + lc;
        float4 av = make_float4(0.f,0.f,0.f,0.f);
        {
            int r = m0 + lr;
            if (r < M){
                if (kc + 3 < K) av = *(const float4*)(A + (size_t)r * lda + kc);
                else {
                    if (kc + 0 < K) av.x = A[(size_t)r * lda + kc + 0];
                    if (kc + 1 < K) av.y = A[(size_t)r * lda + kc + 1];
                    if (kc + 2 < K) av.z = A[(size_t)r * lda + kc + 2];
                    if (kc + 3 < K) av.w = A[(size_t)r * lda + kc + 3];
                }
            }
        }
        float4 bv = make_float4(0.f,0.f,0.f,0.f);
        {
            int r = n0 + lr;
            if (r < N){
                if (kc + 3 < K) bv = *(const float4*)(B + (size_t)r * ldb + kc);
                else {
                    if (kc + 0 < K) bv.x = B[(size_t)r * ldb + kc + 0];
                    if (kc + 1 < K) bv.y = B[(size_t)r * ldb + kc + 1];
                    if (kc + 2 < K) bv.z = B[(size_t)r * ldb + kc + 2];
                    if (kc + 3 < K) bv.w = B[(size_t)r * ldb + kc + 3];
                }
            }
        }
        As[lc + 0][lr] = av.x; As[lc + 1][lr] = av.y; As[lc + 2][lr] = av.z; As[lc + 3][lr] = av.w;
        Bs[lc + 0][lr] = bv.x; Bs[lc + 1][lr] = bv.y; Bs[lc + 2][lr] = bv.z; Bs[lc + 3][lr] = bv.w;
        __syncthreads();
#pragma unroll
        for (int k = 0; k < 8; k++){
            float a[8];
            *(float4*)&a[0] = *(const float4*)&As[k][ty * 8];
            *(float4*)&a[4] = *(const float4*)&As[k][ty * 8 + 4];
            ull bp[4];
            {
                const ull* bq = (const ull*)&Bs[k][tx * 8];   // 32B-aligned
                bp[0] = bq[0]; bp[1] = bq[1]; bp[2] = bq[2]; bp[3] = bq[3];
            }
#pragma unroll
            for (int i2 = 0; i2 < 8; i2++){
                ull ad = dup2(a[i2]);
                acc2[i2][0] = fma2(ad, bp[0], acc2[i2][0]);
                acc2[i2][1] = fma2(ad, bp[1], acc2[i2][1]);
                acc2[i2][2] = fma2(ad, bp[2], acc2[i2][2]);
                acc2[i2][3] = fma2(ad, bp[3], acc2[i2][3]);
            }
        }
        __syncthreads();
    }
#pragma unroll
    for (int i2 = 0; i2 < 8; i2++){
        int m = m0 + ty * 8 + i2;
        if (m < M){
#pragma unroll
            for (int jp = 0; jp < 4; jp++){
                int n = n0 + tx * 8 + 2 * jp;
                if (n + 1 < N){
                    float2 v = make_float2(lo32f(acc2[i2][jp]) + bias[n],
                                           hi32f(acc2[i2][jp]) + bias[n + 1]);
                    *(float2*)(C + (size_t)m * ldc + n) = v;
                } else if (n < N){
                    C[(size_t)m * ldc + n] = lo32f(acc2[i2][jp]) + bias[n];
                }
            }
        }
    }
}

// ---------------- bidirectional LSTM recurrence (one layer, both directions) ----------------
// EXACT R8 structure (best known, 10.92 ms): grid = 2*NBLK CTAs, 256 threads.
// CTA `blk` of direction `dir` owns h[blk*8, blk*8+8): 32 gate rows x 8 column slices.
// Handshake: atomic 8B {tag=t+1, h_bits} via st.global.cg.b64 (single coalesced
// 64B publish from tid<8); consumers poll ld.global.cg.v2.b64 for exact tag.
__global__ __launch_bounds__(256, 1) void lstm_rec(
    const float* __restrict__ preF, const float* __restrict__ preB,
    const float* __restrict__ whhF, const float* __restrict__ whhB,
    float* __restrict__ hsOut,      // [L,1024], fwd -> 0..511, bwd -> 512..1023
    ull* __restrict__ hb)           // [2 dirs][LSEQ][512] packed {tag,h}
{
    const int dir = blockIdx.x >> 6;
    const int blk = blockIdx.x & 63;
    const float* pre = dir ? preB : preF;
    const float* whh = dir ? whhB : whhF;
    ull* hbd = hb + (size_t)dir * LSEQ * HID;

    const int tid  = threadIdx.x;
    const int row  = tid >> 3;          // 0..31 local gate row
    const int cs   = tid & 7;           // 0..7 column slice
    const int gate = row >> 3;          // 0..3 (i,f,g,o)
    const int ii   = row & 7;           // 0..7 h index within CTA
    const int grow = gate * HID + blk * 8 + ii;

    // register-resident packed weight slice: whh[grow][cs*64 .. cs*64+64) as 32 f32x2
    ull wpk[32];
    {
        const float2* wr = (const float2*)(whh + (size_t)grow * HID + cs * 64);
#pragma unroll
        for (int k = 0; k < 32; k++){
            float2 v = wr[k];
            wpk[k] = ((ull)__float_as_uint(v.y) << 32) | (ull)__float_as_uint(v.x);
        }
    }

    __shared__ __align__(16) float sh_h[8 * 68];   // 64-blocks padded by 4 floats
    __shared__ float sg[32];
    for (int k = tid; k < 8 * 68; k += 256) sh_h[k] = 0.f;
    float c = 0.f;                                  // cell state (threads tid<8)
    __syncthreads();

    float preCur = 0.f;
    if (cs == 0){
        int tt0 = dir ? (LSEQ - 1) : 0;
        preCur = pre[(size_t)tt0 * GATES + grow];
    }

    for (int t = 0; t < LSEQ; t++){
        const int tt = dir ? (LSEQ - 1 - t) : t;

        // ---- acquire h(t-1): poll packed {tag,h} words; accept only on exact tag match ----
        if (t > 0){
            const ull* p = hbd + (size_t)(t - 1) * HID + 2 * tid;  // 16B aligned
            const unsigned expTag = (unsigned)t;     // step t-1 published with tag t
            ull q0, q1;
            do {
                asm volatile("ld.global.cg.v2.b64 {%0,%1}, [%2];"
                             : "=l"(q0), "=l"(q1) : "l"(p) : "memory");
            } while ((unsigned)(q0 >> 32) != expTag || (unsigned)(q1 >> 32) != expTag);
            float2 hv = make_float2(__uint_as_float((unsigned)q0),
                                    __uint_as_float((unsigned)q1));
            *(float2*)(sh_h + 2 * tid + 4 * (tid >> 5)) = hv;   // padded layout (+4 per 64)
        }
        __syncthreads();   // sh_h ready; also orders vs previous-step sg use

        // prefetch next step's pre-activation (overlaps with the dot product)
        float preNext = 0.f;
        if (cs == 0 && t + 1 < LSEQ){
            int ttn = dir ? (LSEQ - 2 - t) : (t + 1);
            preNext = pre[(size_t)ttn * GATES + grow];
        }

        // 64-wide slice of the 512-dot: 32 packed f32x2 FMAs over 4 accumulators
        ull a0 = 0ull, a1 = 0ull, a2 = 0ull, a3 = 0ull;
        {
            const ulonglong2* hp = (const ulonglong2*)(sh_h + cs * 68);
#pragma unroll
            for (int k = 0; k < 8; k += 4){
                ulonglong2 u0 = hp[k + 0], u1 = hp[k + 1], u2 = hp[k + 2], u3 = hp[k + 3];
                a0 = fma2(wpk[4*k + 0], u0.x, a0); a0 = fma2(wpk[4*k + 1], u0.y, a0);
                a1 = fma2(wpk[4*k + 2], u1.x, a1); a1 = fma2(wpk[4*k + 3], u1.y, a1);
                a2 = fma2(wpk[4*k + 4], u2.x, a2); a2 = fma2(wpk[4*k + 5], u2.y, a2);
                a3 = fma2(wpk[4*k + 6], u3.x, a3); a3 = fma2(wpk[4*k + 7], u3.y, a3);
            }
        }
        float sum = ((lo32f(a0) + hi32f(a0)) + (lo32f(a1) + hi32f(a1)))
                  + ((lo32f(a2) + hi32f(a2)) + (lo32f(a3) + hi32f(a3)));
        sum += __shfl_down_sync(0xffffffffu, sum, 4);
        sum += __shfl_down_sync(0xffffffffu, sum, 2);
        sum += __shfl_down_sync(0xffffffffu, sum, 1);
        if (cs == 0) sg[row] = sum + preCur;
        __syncthreads();

        if (tid < 8){
            float zi = sg[tid], zf = sg[8 + tid], zg = sg[16 + tid], zo = sg[24 + tid];
            float ei = __expf(-zi), ef = __expf(-zf), eo = __expf(-zo), eg = __expf(-2.f * zg);
            float ig = __fdividef(1.f, 1.f + ei);
            float fg = __fdividef(1.f, 1.f + ef);
            float og = __fdividef(1.f, 1.f + eo);
            float tg = (1.f - eg) * __fdividef(1.f, 1.f + eg);
            c = fg * c + ig * tg;
            float e2 = __expf(-2.f * c);
            float th = (1.f - e2) * __fdividef(1.f, 1.f + e2);
            float h  = og * th;
            int hidx = blk * 8 + tid;
            ull v = ((ull)(unsigned)(t + 1) << 32) | (ull)__float_as_uint(h);
            asm volatile("st.global.cg.b64 [%0], %1;"
                         :: "l"(hbd + (size_t)t * HID + hidx), "l"(v) : "memory");
            hsOut[(size_t)tt * 1024 + dir * HID + hidx] = h;
        }
        preCur = preNext;
    }
}

// ---------------- CRF negative log-likelihood ----------------
// block (32,24): warp j computes alpha_new[j] each step; shfl.bfly reductions.
// Double-buffered alpha: one __syncthreads per step.
__global__ void crf_kernel(const float* __restrict__ emis, const int* __restrict__ tags,
                           const float* __restrict__ startT, const float* __restrict__ endT,
                           const float* __restrict__ trans, float* __restrict__ out)
{
    const int i = threadIdx.x;   // 0..31 (prev tag lane)
    const int j = threadIdx.y;   // 0..23 (current tag)
    const int tid = j * 32 + i;
    __shared__ float alpha[2][TTAG];
    __shared__ float red[TTAG];

    // numerator (gold path score), parallel over t
    float acc = 0.f;
    for (int t = tid; t < LSEQ; t += 768){
        acc += emis[t * TTAG + tags[t]];
        if (t > 0) acc += trans[tags[t - 1] * TTAG + tags[t]];
    }
#pragma unroll
    for (int d = 16; d; d >>= 1) acc += __shfl_xor_sync(0xffffffffu, acc, d);
    if (i == 0) red[j] = acc;

    const float trj = (i < TTAG) ? trans[i * TTAG + j] : 0.f;
    if (i == 0) alpha[0][j] = startT[j] + emis[j];
    __syncthreads();

    float num = 0.f;
    if (tid == 0){
        for (int q = 0; q < TTAG; q++) num += red[q];
        num += startT[tags[0]] + endT[tags[LSEQ - 1]];
    }

    for (int t = 1; t < LSEQ; t++){
        const int cur = (t - 1) & 1, nxt = t & 1;
        float v = (i < TTAG) ? (alpha[cur][i] + trj) : -3.0e38f;
        float m = v;
#pragma unroll
        for (int d = 16; d; d >>= 1) m = fmaxf(m, __shfl_xor_sync(0xffffffffu, m, d));
        float e = (i < TTAG) ? __expf(v - m) : 0.f;
#pragma unroll
        for (int d = 16; d; d >>= 1) e += __shfl_xor_sync(0xffffffffu, e, d);
        if (i == 0) alpha[nxt][j] = m + __logf(e) + emis[t * TTAG + j];
        __syncthreads();   // alpha[nxt] visible; alpha[cur] free for t+1's writes
    }

    if (tid == 0){
        const float* af = alpha[(LSEQ - 1) & 1];
        float m = -3.0e38f;
        for (int q = 0; q < TTAG; q++) m = fmaxf(m, af[q] + endT[q]);
        float s = 0.f;
        for (int q = 0; q < TTAG; q++) s += __expf(af[q] + endT[q] - m);
        out[0] = (m + __logf(s)) - num;
    }
}

// ---------------- launch ----------------
extern "C" void kernel_launch(void* const* d_in, const int* in_sizes, int n_in,
                              void* d_out, int out_size)
{
    (void)in_sizes; (void)n_in; (void)out_size;
    const float* emb    = (const float*)d_in[0];
    const float* wih0f  = (const float*)d_in[1];
    const float* whh0f  = (const float*)d_in[2];
    const float* b0f    = (const float*)d_in[3];
    const float* wih0b  = (const float*)d_in[4];
    const float* whh0b  = (const float*)d_in[5];
    const float* b0b    = (const float*)d_in[6];
    const float* wih1f  = (const float*)d_in[7];
    const float* whh1f  = (const float*)d_in[8];
    const float* b1f    = (const float*)d_in[9];
    const float* wih1b  = (const float*)d_in[10];
    const float* whh1b  = (const float*)d_in[11];
    const float* b1b    = (const float*)d_in[12];
    const float* wout   = (const float*)d_in[13];
    const float* bout   = (const float*)d_in[14];
    const float* startT = (const float*)d_in[15];
    const float* endT   = (const float*)d_in[16];
    const float* trans  = (const float*)d_in[17];
    const int*   sent   = (const int*)d_in[18];
    const int*   tags   = (const int*)d_in[19];

    float *x, *preA, *preB, *hs0, *hs1, *emis;
    ull* hbuf;
    cudaGetSymbolAddress((void**)&x,    g_x);
    cudaGetSymbolAddress((void**)&preA, g_preA);
    cudaGetSymbolAddress((void**)&preB, g_preB);
    cudaGetSymbolAddress((void**)&hs0,  g_hs0);
    cudaGetSymbolAddress((void**)&hs1,  g_hs1);
    cudaGetSymbolAddress((void**)&emis, g_emis);
    cudaGetSymbolAddress((void**)&hbuf, g_hbuf);

    // reset handshake tags + embedding gather
    fill_tags<<<4096, 256>>>();
    gather_kernel<<<LSEQ, 128>>>(emb, sent);

    // layer 0: input projections, then both-direction recurrence
    sgemm_nt<<<dim3(16, 32), 256>>>(LSEQ, GATES, EDIM, x, EDIM, wih0f, EDIM, b0f, preA, GATES);
    sgemm_nt<<<dim3(16, 32), 256>>>(LSEQ, GATES, EDIM, x, EDIM, wih0b, EDIM, b0b, preB, GATES);
    lstm_rec<<<2 * NBLK, 256>>>(preA, preB, whh0f, whh0b, hs0, hbuf);

    // layer 1
    sgemm_nt<<<dim3(16, 32), 256>>>(LSEQ, GATES, 1024, hs0, 1024, wih1f, 1024, b1f, preA, GATES);
    sgemm_nt<<<dim3(16, 32), 256>>>(LSEQ, GATES, 1024, hs0, 1024, wih1b, 1024, b1b, preB, GATES);
    lstm_rec<<<2 * NBLK, 256>>>(preA, preB, whh1f, whh1b, hs1, hbuf + (size_t)2 * LSEQ * HID);

    // emissions + CRF
    sgemm_nt<<<dim3(1, 32), 256>>>(LSEQ, TTAG, 1024, hs1, 1024, wout, 1024, bout, emis, TTAG);
    crf_kernel<<<1, dim3(32, 24)>>>(emis, tags, startT, endT, trans, (float*)d_out);
}